// round 14
// baseline (speedup 1.0000x reference)
#include <cuda_runtime.h>
#include <cuda_bf16.h>
#include <cuda_fp16.h>
#include <cstdint>

// ---------------------------------------------------------------------------
// Problem constants
// ---------------------------------------------------------------------------
#define BB 8
#define SS 2048
#define HH 1024
#define MM (BB * SS)      // 16384
#define KK HH             // 1024
#define NN (3 * HH)       // 3072

// Scratch (__device__ globals: allocation-guard-safe)
__device__ float         g_xc[(size_t)MM * HH];        // middle third, fp32
__device__ __half        g_gates[(size_t)MM * 2 * HH]; // [M][xf HH | xr HH] fp16
__device__ __nv_bfloat16 g_Ahi[(size_t)MM * KK];
__device__ __nv_bfloat16 g_Alo[(size_t)MM * KK];
__device__ __nv_bfloat16 g_Bhi[(size_t)NN * KK];
__device__ __nv_bfloat16 g_Blo[(size_t)NN * KK];
__device__ unsigned int  g_tilectr;                    // persistent-GEMM work counter

// ---------------------------------------------------------------------------
// Helpers
// ---------------------------------------------------------------------------
__device__ __forceinline__ uint32_t s2u(const void* p) {
    uint32_t a;
    asm("{ .reg .u64 t; cvta.to.shared.u64 t, %1; cvt.u32.u64 %0, t; }"
        : "=r"(a) : "l"(p));
    return a;
}

__device__ __forceinline__ uint32_t sw128(uint32_t o) {
    return o ^ ((o >> 3) & 0x70);
}

#define CP_ASYNC16(smem_u32, gptr)                                      \
    asm volatile("cp.async.cg.shared.global [%0], [%1], 16;"            \
                 :: "r"(smem_u32), "l"(gptr) : "memory")
#define CP_COMMIT() asm volatile("cp.async.commit_group;" ::: "memory")
#define CP_WAIT1()  asm volatile("cp.async.wait_group 1;" ::: "memory")
#define CP_WAIT2()  asm volatile("cp.async.wait_group 2;" ::: "memory")

__device__ __forceinline__ void ldmatrix_x4(uint32_t* r, uint32_t addr) {
    asm volatile("ldmatrix.sync.aligned.m8n8.x4.shared.b16 {%0,%1,%2,%3}, [%4];"
                 : "=r"(r[0]), "=r"(r[1]), "=r"(r[2]), "=r"(r[3])
                 : "r"(addr));
}

__device__ __forceinline__ void mma_bf16(float* c, const uint32_t* a,
                                         uint32_t b0, uint32_t b1) {
    asm volatile(
        "mma.sync.aligned.m16n8k16.row.col.f32.bf16.bf16.f32 "
        "{%0,%1,%2,%3}, {%4,%5,%6,%7}, {%8,%9}, {%0,%1,%2,%3};"
        : "+f"(c[0]), "+f"(c[1]), "+f"(c[2]), "+f"(c[3])
        : "r"(a[0]), "r"(a[1]), "r"(a[2]), "r"(a[3]), "r"(b0), "r"(b1));
}

// ---------------------------------------------------------------------------
// Fused conversion: A split + W transpose split + counter reset
// ---------------------------------------------------------------------------
#define NA_BLK (MM * KK / 1024)             // 16384
#define NW_BLK ((NN / 32) * (KK / 32))      // 3072

__global__ void __launch_bounds__(256) cvt_fused(const float* __restrict__ x,
                                                 const float* __restrict__ W) {
    if (blockIdx.x == 0 && threadIdx.x == 0) g_tilectr = 0;

    if (blockIdx.x < NA_BLK) {
        size_t i = ((size_t)blockIdx.x * 256 + threadIdx.x) * 4;
        float4 v = *(const float4*)(x + i);
        float f[4] = {v.x, v.y, v.z, v.w};
        __nv_bfloat16 hi[4], lo[4];
#pragma unroll
        for (int j = 0; j < 4; j++) {
            hi[j] = __float2bfloat16(f[j]);
            lo[j] = __float2bfloat16(f[j] - __bfloat162float(hi[j]));
        }
        __nv_bfloat162 h0(hi[0], hi[1]), h1(hi[2], hi[3]);
        __nv_bfloat162 l0(lo[0], lo[1]), l1(lo[2], lo[3]);
        *reinterpret_cast<__nv_bfloat162*>(g_Ahi + i)     = h0;
        *reinterpret_cast<__nv_bfloat162*>(g_Ahi + i + 2) = h1;
        *reinterpret_cast<__nv_bfloat162*>(g_Alo + i)     = l0;
        *reinterpret_cast<__nv_bfloat162*>(g_Alo + i + 2) = l1;
    } else {
        __shared__ float s[32][33];
        const int bw = blockIdx.x - NA_BLK;
        const int n0 = (bw % (NN / 32)) * 32;
        const int k0 = (bw / (NN / 32)) * 32;
        const int tx = threadIdx.x & 31, ty = threadIdx.x >> 5;
#pragma unroll
        for (int i = 0; i < 4; i++)
            s[ty + 8 * i][tx] = W[(size_t)(k0 + ty + 8 * i) * NN + n0 + tx];
        __syncthreads();
#pragma unroll
        for (int i = 0; i < 4; i++) {
            const int n = n0 + ty + 8 * i;
            const int k = k0 + tx;
            const float f = s[tx][ty + 8 * i];
            __nv_bfloat16 hi = __float2bfloat16(f);
            __nv_bfloat16 lo = __float2bfloat16(f - __bfloat162float(hi));
            g_Bhi[(size_t)n * KK + k] = hi;
            g_Blo[(size_t)n * KK + k] = lo;
        }
    }
}

// ---------------------------------------------------------------------------
// Persistent GEMM: 128x128 tiles, BK=64, 3-stage cp.async ring that carries
// across tile boundaries (48 chunks % 3 == 0), dynamic tile claiming.
// ---------------------------------------------------------------------------
#define BK 64
#define STAGE_B 32768
#define NSTAGE 3
#define GEMM_SMEM (NSTAGE * STAGE_B)        // 96 KB
#define NCHUNK (3 * KK / BK)                // 48
#define NTILES (NN / 128)                   // 24
#define TOT_TILES ((MM / 128) * NTILES)     // 3072
#define PERSIST_CTAS 304                    // 2 per SM on 152 SMs

__device__ __forceinline__ void load_chunk(int tile, int c, int tid,
                                           uint32_t sb) {
    const int bm = (tile / NTILES) * 128;
    const int bn = (tile % NTILES) * 128;
    const int third = c >> 4;
    const int kk0 = (c & 15) * BK;
    const __nv_bfloat16* Ap = (third == 2) ? g_Alo : g_Ahi;
    const __nv_bfloat16* Bp = (third == 1) ? g_Blo : g_Bhi;
    const uint32_t dst = sb + (uint32_t)(c % NSTAGE) * STAGE_B;
#pragma unroll
    for (int i = 0; i < 4; i++) {
        const int idx = tid + i * 256;
        const int row = idx >> 3;
        const int c16 = idx & 7;
        const uint32_t so = sw128((uint32_t)(row * 128 + c16 * 16));
        CP_ASYNC16(dst + so,         Ap + (size_t)(bm + row) * KK + kk0 + c16 * 8);
        CP_ASYNC16(dst + 16384 + so, Bp + (size_t)(bn + row) * KK + kk0 + c16 * 8);
    }
}

__global__ void __launch_bounds__(256, 2) sru_mma_gemm() {
    extern __shared__ __align__(128) char smr[];
    __shared__ int s_tile, s_next;
    const uint32_t sb = s2u(smr);
    const int tid = threadIdx.x;
    const int wid = tid >> 5;
    const int l = tid & 31;
    const int wm = wid >> 2;
    const int wn = wid & 3;

    // Tile-independent swizzled ldmatrix offsets
    uint32_t aoff[4], boff[2];
#pragma unroll
    for (int mt = 0; mt < 4; mt++) {
        const uint32_t o = (uint32_t)((wm * 64 + mt * 16 + (l & 15)) * 128 +
                                      (l >> 4) * 16);
        aoff[mt] = sw128(o);
    }
#pragma unroll
    for (int nb = 0; nb < 2; nb++) {
        const int n = wn * 32 + nb * 16 + ((l >> 4) << 3) + (l & 7);
        const uint32_t o = (uint32_t)(n * 128 + ((l >> 3) & 1) * 16);
        boff[nb] = 16384u + sw128(o);
    }

    // Claim first tile
    if (tid == 0) s_tile = (int)atomicAdd(&g_tilectr, 1u);
    __syncthreads();
    int tile = s_tile;
    if (tile >= TOT_TILES) return;

    // Prologue: chunks 0,1 of first tile
    load_chunk(tile, 0, tid, sb);
    CP_COMMIT();
    load_chunk(tile, 1, tid, sb);
    CP_COMMIT();

    for (;;) {
        float acc[4][4][4];
#pragma unroll
        for (int i = 0; i < 4; i++)
#pragma unroll
            for (int j = 0; j < 4; j++)
#pragma unroll
                for (int k = 0; k < 4; k++) acc[i][j][k] = 0.0f;

        int tnext = TOT_TILES;
        for (int c = 0; c < NCHUNK; c++) {
            CP_WAIT1();
            __syncthreads();

            if (c == 0) {
                if (tid == 0) s_next = (int)atomicAdd(&g_tilectr, 1u);
            } else {
                tnext = s_next;   // published by the c>=1 __syncthreads above
            }

            if (c < NCHUNK - 2) {
                load_chunk(tile, c + 2, tid, sb);
            } else if (tnext < TOT_TILES) {
                // next tile's chunk (c+2-48): stage index continues mod 3
                load_chunk(tnext, c + 2 - NCHUNK, tid, sb);
            }
            CP_COMMIT();

            const uint32_t base = sb + (uint32_t)(c % NSTAGE) * STAGE_B;
#pragma unroll
            for (int k16 = 0; k16 < 4; k16++) {
                const uint32_t kx = (uint32_t)(k16 * 32);
                uint32_t a[4][4], b[2][4];
#pragma unroll
                for (int mt = 0; mt < 4; mt++)
                    ldmatrix_x4(a[mt], base + (aoff[mt] ^ kx));
#pragma unroll
                for (int nb = 0; nb < 2; nb++)
                    ldmatrix_x4(b[nb], base + (boff[nb] ^ kx));
#pragma unroll
                for (int mt = 0; mt < 4; mt++)
#pragma unroll
                    for (int nt = 0; nt < 4; nt++)
                        mma_bf16(acc[mt][nt], a[mt], b[nt >> 1][(nt & 1) * 2],
                                 b[nt >> 1][(nt & 1) * 2 + 1]);
            }
        }

        // Epilogue: third 1 -> fp32 g_xc; thirds 0/2 -> fp16 g_gates
        {
            const int bm = (tile / NTILES) * 128;
            const int bn = (tile % NTILES) * 128;
            const int g = l >> 2;
            const int t4 = l & 3;
            const int third = bn >> 10;
            const int nloc = bn & 1023;

            if (third == 1) {
#pragma unroll
                for (int mt = 0; mt < 4; mt++) {
                    const size_t r0 = (size_t)(bm + wm * 64 + mt * 16 + g);
#pragma unroll
                    for (int nt = 0; nt < 4; nt++) {
                        const int col = nloc + wn * 32 + nt * 8 + t4 * 2;
                        float2 v0 = make_float2(acc[mt][nt][0], acc[mt][nt][1]);
                        float2 v1 = make_float2(acc[mt][nt][2], acc[mt][nt][3]);
                        *reinterpret_cast<float2*>(g_xc + r0 * HH + col) = v0;
                        *reinterpret_cast<float2*>(g_xc + (r0 + 8) * HH + col) = v1;
                    }
                }
            } else {
                const int plane = (third == 0) ? 0 : 1;
#pragma unroll
                for (int mt = 0; mt < 4; mt++) {
                    const size_t r0 = (size_t)(bm + wm * 64 + mt * 16 + g);
#pragma unroll
                    for (int nt = 0; nt < 4; nt++) {
                        const int col = nloc + wn * 32 + nt * 8 + t4 * 2;
                        __half2 v0 = __floats2half2_rn(acc[mt][nt][0],
                                                       acc[mt][nt][1]);
                        __half2 v1 = __floats2half2_rn(acc[mt][nt][2],
                                                       acc[mt][nt][3]);
                        *reinterpret_cast<__half2*>(g_gates + r0 * 2 * HH +
                                                    (size_t)plane * HH + col) = v0;
                        *reinterpret_cast<__half2*>(g_gates + (r0 + 8) * 2 * HH +
                                                    (size_t)plane * HH + col) = v1;
                    }
                }
            }
        }

        if (tnext >= TOT_TILES) break;
        tile = tnext;   // its chunks 0,1 are already in flight in stages 0,1
    }
}

// ---------------------------------------------------------------------------
// Scan (sequential, after GEMM): one warp / 32 channels, cp.async pipeline,
// mixed fp32/fp16 records (R10 configuration: TSTG=16)
// ---------------------------------------------------------------------------
#define TSTG 16
#define SNSTG 4
#define REC_B 384
#define STAGE_BYTES (TSTG * REC_B)          // 6144

__device__ __forceinline__ float fast_tanh(float x) {
    float r;
    asm("tanh.approx.f32 %0, %1;" : "=f"(r) : "f"(x));
    return r;
}

__global__ void __launch_bounds__(32) sru_scan_kernel(
    const float* __restrict__ x, const float* __restrict__ vf,
    const float* __restrict__ vr, const float* __restrict__ bf,
    const float* __restrict__ br, float* __restrict__ out) {
    __shared__ __align__(16) char s[SNSTG * STAGE_BYTES];  // 24576 B

    const int l = threadIdx.x;
    const int b = blockIdx.x >> 5;
    const int h0 = (blockIdx.x & 31) * 32;
    const int h = h0 + l;

    const char* xc_base = (const char*)g_xc + (size_t)b * SS * 4096 + h0 * 4;
    const char* xv_base = (const char*)x + (size_t)b * SS * 4096 + h0 * 4;
    const char* gf_base = (const char*)g_gates + (size_t)b * SS * 4096 + h0 * 2;
    const char* gr_base = gf_base + HH * 2;

    // Per-lane chunk table: 384 chunks/stage = 12 per lane
    const char* srcp[12];
    uint32_t dsto[12];
#pragma unroll
    for (int i = 0; i < 12; i++) {
        const int gch = i * 32 + l;
        const int t = gch / 24;
        const int j = gch - t * 24;
        const char* p;
        if (j < 8)       p = xc_base + (size_t)t * 4096 + j * 16;
        else if (j < 16) p = xv_base + (size_t)t * 4096 + (j - 8) * 16;
        else if (j < 20) p = gf_base + (size_t)t * 4096 + (j - 16) * 16;
        else             p = gr_base + (size_t)t * 4096 + (j - 20) * 16;
        srcp[i] = p;
        dsto[i] = (uint32_t)(t * REC_B + j * 16);
    }
    const uint32_t sbase = s2u(s);

    const float vfh = 0.5f * vf[h];
    const float vrh = 0.5f * vr[h];
    const float bfh = 0.5f * bf[h];
    const float brh = 0.5f * br[h];
    float* yp = out + (size_t)b * SS * HH + h;

#define LOAD_STAGE(st)                                                        \
    {                                                                         \
        const uint32_t d0 = sbase + (uint32_t)((st) & (SNSTG - 1)) * STAGE_BYTES; \
        const size_t go = (size_t)(st) * (TSTG * 4096);                       \
        _Pragma("unroll") for (int i = 0; i < 12; i++) {                      \
            CP_ASYNC16(d0 + dsto[i], srcp[i] + go);                           \
        }                                                                     \
        CP_COMMIT();                                                          \
    }

    LOAD_STAGE(0);
    LOAD_STAGE(1);
    LOAD_STAGE(2);

    float c = 0.0f;
    const int NST = SS / TSTG;  // 128
    for (int st = 0; st < NST; st++) {
        CP_WAIT2();
        __syncwarp();

        if (st + 3 < NST) {
            LOAD_STAGE(st + 3);
        } else {
            CP_COMMIT();
        }

        const char* sp = s + (st & (SNSTG - 1)) * STAGE_BYTES;
        const int tb = st * TSTG;
#pragma unroll
        for (int t = 0; t < TSTG; t++) {
            const char* rp = sp + t * REC_B;
            const float xc = *(const float*)(rp + l * 4);
            const float xv = *(const float*)(rp + 128 + l * 4);
            const float xf = __half2float(*(const __half*)(rp + 256 + l * 2));
            const float xr = __half2float(*(const __half*)(rp + 320 + l * 2));

            const float xfh = fmaf(0.5f, xf, bfh);
            const float xch = 0.5f * xc;
            const float xrh = fmaf(0.5f, xr, brh);
            const float xvh = 0.5f * xv;

            const float ct = c;
            const float thf = fast_tanh(fmaf(vfh, ct, xfh));
            const float thr = fast_tanh(fmaf(vrh, ct, xrh));
            const float d = fmaf(0.5f, ct, -xch);
            const float m = fmaf(0.5f, ct, xch);
            c = fmaf(thf, d, m);
            const float dr = fmaf(0.5f, c, -xvh);
            const float mr = fmaf(0.5f, c, xvh);
            yp[(size_t)(tb + t) * HH] = fmaf(thr, dr, mr);
        }
        __syncwarp();
    }

    out[(size_t)BB * SS * HH + (size_t)b * HH + h] = c;
}

// ---------------------------------------------------------------------------
// Launch: sequential — cvt -> persistent GEMM -> scan
// ---------------------------------------------------------------------------
extern "C" void kernel_launch(void* const* d_in, const int* in_sizes, int n_in,
                              void* d_out, int out_size) {
    const float* x  = (const float*)d_in[0];
    const float* W  = (const float*)d_in[1];
    const float* vf = (const float*)d_in[2];
    const float* vr = (const float*)d_in[3];
    const float* bf = (const float*)d_in[4];
    const float* br = (const float*)d_in[5];
    float* out = (float*)d_out;

    static int inited = 0;
    if (!inited) {
        cudaFuncSetAttribute(sru_mma_gemm,
                             cudaFuncAttributeMaxDynamicSharedMemorySize,
                             GEMM_SMEM);
        inited = 1;
    }

    cvt_fused<<<NA_BLK + NW_BLK, 256>>>(x, W);
    sru_mma_gemm<<<PERSIST_CTAS, 256, GEMM_SMEM>>>();
    sru_scan_kernel<<<(BB * HH) / 32, 32>>>(x, vf, vr, bf, br, out);
}

// round 16
// speedup vs baseline: 1.6374x; 1.6374x over previous
#include <cuda_runtime.h>
#include <cuda_bf16.h>
#include <cuda_fp16.h>
#include <cstdint>

// ---------------------------------------------------------------------------
// Problem constants
// ---------------------------------------------------------------------------
#define BB 8
#define SS 2048
#define HH 1024
#define MM (BB * SS)      // 16384
#define KK HH             // 1024
#define NN (3 * HH)       // 3072

// Scratch (__device__ globals: allocation-guard-safe)
__device__ float         g_xc[(size_t)MM * HH];        // middle third, fp32
__device__ __half        g_gates[(size_t)MM * 2 * HH]; // [M][xf HH | xr HH] fp16
__device__ __nv_bfloat16 g_Ahi[(size_t)MM * KK];
__device__ __nv_bfloat16 g_Alo[(size_t)MM * KK];
__device__ __nv_bfloat16 g_Bhi[(size_t)NN * KK];
__device__ __nv_bfloat16 g_Blo[(size_t)NN * KK];
__device__ unsigned int  g_flags[MM / 128];            // per-M-tile N-tile counters

// ---------------------------------------------------------------------------
// Helpers
// ---------------------------------------------------------------------------
__device__ __forceinline__ uint32_t s2u(const void* p) {
    uint32_t a;
    asm("{ .reg .u64 t; cvta.to.shared.u64 t, %1; cvt.u32.u64 %0, t; }"
        : "=r"(a) : "l"(p));
    return a;
}

__device__ __forceinline__ uint32_t sw128(uint32_t o) {
    return o ^ ((o >> 3) & 0x70);
}

#define CP_ASYNC16(smem_u32, gptr)                                      \
    asm volatile("cp.async.cg.shared.global [%0], [%1], 16;"            \
                 :: "r"(smem_u32), "l"(gptr) : "memory")
#define CP_COMMIT() asm volatile("cp.async.commit_group;" ::: "memory")
#define CP_WAIT1()  asm volatile("cp.async.wait_group 1;" ::: "memory")
#define CP_WAIT2()  asm volatile("cp.async.wait_group 2;" ::: "memory")

__device__ __forceinline__ void ldmatrix_x4(uint32_t* r, uint32_t addr) {
    asm volatile("ldmatrix.sync.aligned.m8n8.x4.shared.b16 {%0,%1,%2,%3}, [%4];"
                 : "=r"(r[0]), "=r"(r[1]), "=r"(r[2]), "=r"(r[3])
                 : "r"(addr));
}

__device__ __forceinline__ void mma_bf16(float* c, const uint32_t* a,
                                         uint32_t b0, uint32_t b1) {
    asm volatile(
        "mma.sync.aligned.m16n8k16.row.col.f32.bf16.bf16.f32 "
        "{%0,%1,%2,%3}, {%4,%5,%6,%7}, {%8,%9}, {%0,%1,%2,%3};"
        : "+f"(c[0]), "+f"(c[1]), "+f"(c[2]), "+f"(c[3])
        : "r"(a[0]), "r"(a[1]), "r"(a[2]), "r"(a[3]), "r"(b0), "r"(b1));
}

__device__ __forceinline__ uint32_t ld_acquire(const unsigned int* p) {
    uint32_t v;
    asm volatile("ld.acquire.gpu.global.b32 %0, [%1];" : "=r"(v) : "l"(p)
                 : "memory");
    return v;
}
__device__ __forceinline__ void red_release_add(unsigned int* p, uint32_t v) {
    asm volatile("red.release.gpu.global.add.u32 [%0], %1;" :: "l"(p), "r"(v)
                 : "memory");
}

// ---------------------------------------------------------------------------
// Fused conversion: A split + W transpose split + flag zeroing
// ---------------------------------------------------------------------------
#define NA_BLK (MM * KK / 1024)             // 16384
#define NW_BLK ((NN / 32) * (KK / 32))      // 3072

__global__ void __launch_bounds__(256) cvt_fused(const float* __restrict__ x,
                                                 const float* __restrict__ W) {
    if (blockIdx.x == 0 && threadIdx.x < MM / 128) g_flags[threadIdx.x] = 0;

    if (blockIdx.x < NA_BLK) {
        size_t i = ((size_t)blockIdx.x * 256 + threadIdx.x) * 4;
        float4 v = *(const float4*)(x + i);
        float f[4] = {v.x, v.y, v.z, v.w};
        __nv_bfloat16 hi[4], lo[4];
#pragma unroll
        for (int j = 0; j < 4; j++) {
            hi[j] = __float2bfloat16(f[j]);
            lo[j] = __float2bfloat16(f[j] - __bfloat162float(hi[j]));
        }
        __nv_bfloat162 h0(hi[0], hi[1]), h1(hi[2], hi[3]);
        __nv_bfloat162 l0(lo[0], lo[1]), l1(lo[2], lo[3]);
        *reinterpret_cast<__nv_bfloat162*>(g_Ahi + i)     = h0;
        *reinterpret_cast<__nv_bfloat162*>(g_Ahi + i + 2) = h1;
        *reinterpret_cast<__nv_bfloat162*>(g_Alo + i)     = l0;
        *reinterpret_cast<__nv_bfloat162*>(g_Alo + i + 2) = l1;
    } else {
        __shared__ float s[32][33];
        const int bw = blockIdx.x - NA_BLK;
        const int n0 = (bw % (NN / 32)) * 32;
        const int k0 = (bw / (NN / 32)) * 32;
        const int tx = threadIdx.x & 31, ty = threadIdx.x >> 5;
#pragma unroll
        for (int i = 0; i < 4; i++)
            s[ty + 8 * i][tx] = W[(size_t)(k0 + ty + 8 * i) * NN + n0 + tx];
        __syncthreads();
#pragma unroll
        for (int i = 0; i < 4; i++) {
            const int n = n0 + ty + 8 * i;
            const int k = k0 + tx;
            const float f = s[tx][ty + 8 * i];
            __nv_bfloat16 hi = __float2bfloat16(f);
            __nv_bfloat16 lo = __float2bfloat16(f - __bfloat162float(hi));
            g_Bhi[(size_t)n * KK + k] = hi;
            g_Blo[(size_t)n * KK + k] = lo;
        }
    }
}

// ---------------------------------------------------------------------------
// Joint kernel: blocks [0, 3072) GEMM tiles; blocks [3072, 3328) scan warps
// ---------------------------------------------------------------------------
#define BK 64
#define STAGE_B 32768
#define NSTAGE 3
#define GEMM_SMEM (NSTAGE * STAGE_B)        // 96 KB
#define NCHUNK (3 * KK / BK)                // 48
#define NTILES (NN / 128)                   // 24
#define GEMM_BLOCKS ((MM / 128) * NTILES)   // 3072

#define TSTG 16
#define SNSTG 4
#define REC_B 384
#define STAGE_BYTES (TSTG * REC_B)          // 6144

__device__ __forceinline__ void load_chunk(int c, int tid, int bm, int bn,
                                           uint32_t sb) {
    const int third = c >> 4;
    const int kk0 = (c & 15) * BK;
    const __nv_bfloat16* Ap = (third == 2) ? g_Alo : g_Ahi;
    const __nv_bfloat16* Bp = (third == 1) ? g_Blo : g_Bhi;
    const uint32_t dst = sb + (uint32_t)(c % NSTAGE) * STAGE_B;
#pragma unroll
    for (int i = 0; i < 4; i++) {
        const int idx = tid + i * 256;
        const int row = idx >> 3;
        const int c16 = idx & 7;
        const uint32_t so = sw128((uint32_t)(row * 128 + c16 * 16));
        CP_ASYNC16(dst + so,         Ap + (size_t)(bm + row) * KK + kk0 + c16 * 8);
        CP_ASYNC16(dst + 16384 + so, Bp + (size_t)(bn + row) * KK + kk0 + c16 * 8);
    }
}

__device__ __forceinline__ float fast_tanh(float x) {
    float r;
    asm("tanh.approx.f32 %0, %1;" : "=f"(r) : "f"(x));
    return r;
}

__device__ void gemm_body(char* smr, int bid) {
    const uint32_t sb = s2u(smr);
    const int tid = threadIdx.x;
    const int wid = tid >> 5;
    const int l = tid & 31;
    const int wm = wid >> 2;
    const int wn = wid & 3;
    const int mtile = bid / NTILES;
    const int bm = mtile * 128;
    const int bn = (bid % NTILES) * 128;

    float acc[4][4][4];
#pragma unroll
    for (int i = 0; i < 4; i++)
#pragma unroll
        for (int j = 0; j < 4; j++)
#pragma unroll
            for (int k = 0; k < 4; k++) acc[i][j][k] = 0.0f;

    uint32_t aoff[4], boff[2];
#pragma unroll
    for (int mt = 0; mt < 4; mt++) {
        const uint32_t o = (uint32_t)((wm * 64 + mt * 16 + (l & 15)) * 128 +
                                      (l >> 4) * 16);
        aoff[mt] = sw128(o);
    }
#pragma unroll
    for (int nb = 0; nb < 2; nb++) {
        const int n = wn * 32 + nb * 16 + ((l >> 4) << 3) + (l & 7);
        const uint32_t o = (uint32_t)(n * 128 + ((l >> 3) & 1) * 16);
        boff[nb] = 16384u + sw128(o);
    }

#pragma unroll
    for (int p = 0; p < 2; p++) {
        load_chunk(p, tid, bm, bn, sb);
        CP_COMMIT();
    }

    for (int c = 0; c < NCHUNK; c++) {
        CP_WAIT1();
        __syncthreads();

        if (c + 2 < NCHUNK) load_chunk(c + 2, tid, bm, bn, sb);
        CP_COMMIT();

        const uint32_t base = sb + (uint32_t)(c % NSTAGE) * STAGE_B;
#pragma unroll
        for (int k16 = 0; k16 < 4; k16++) {
            const uint32_t kx = (uint32_t)(k16 * 32);
            uint32_t a[4][4], b[2][4];
#pragma unroll
            for (int mt = 0; mt < 4; mt++)
                ldmatrix_x4(a[mt], base + (aoff[mt] ^ kx));
#pragma unroll
            for (int nb = 0; nb < 2; nb++)
                ldmatrix_x4(b[nb], base + (boff[nb] ^ kx));
#pragma unroll
            for (int mt = 0; mt < 4; mt++)
#pragma unroll
                for (int nt = 0; nt < 4; nt++)
                    mma_bf16(acc[mt][nt], a[mt], b[nt >> 1][(nt & 1) * 2],
                             b[nt >> 1][(nt & 1) * 2 + 1]);
        }
    }

    // Epilogue: third 1 -> fp32 g_xc; thirds 0/2 -> fp16 g_gates
    const int g = l >> 2;
    const int t4 = l & 3;
    const int third = bn >> 10;
    const int nloc = bn & 1023;

    if (third == 1) {
#pragma unroll
        for (int mt = 0; mt < 4; mt++) {
            const size_t r0 = (size_t)(bm + wm * 64 + mt * 16 + g);
#pragma unroll
            for (int nt = 0; nt < 4; nt++) {
                const int col = nloc + wn * 32 + nt * 8 + t4 * 2;
                float2 v0 = make_float2(acc[mt][nt][0], acc[mt][nt][1]);
                float2 v1 = make_float2(acc[mt][nt][2], acc[mt][nt][3]);
                *reinterpret_cast<float2*>(g_xc + r0 * HH + col)       = v0;
                *reinterpret_cast<float2*>(g_xc + (r0 + 8) * HH + col) = v1;
            }
        }
    } else {
        const int plane = (third == 0) ? 0 : 1;
#pragma unroll
        for (int mt = 0; mt < 4; mt++) {
            const size_t r0 = (size_t)(bm + wm * 64 + mt * 16 + g);
#pragma unroll
            for (int nt = 0; nt < 4; nt++) {
                const int col = nloc + wn * 32 + nt * 8 + t4 * 2;
                __half2 v0 = __floats2half2_rn(acc[mt][nt][0], acc[mt][nt][1]);
                __half2 v1 = __floats2half2_rn(acc[mt][nt][2], acc[mt][nt][3]);
                *reinterpret_cast<__half2*>(g_gates + r0 * 2 * HH +
                                            (size_t)plane * HH + col) = v0;
                *reinterpret_cast<__half2*>(g_gates + (r0 + 8) * 2 * HH +
                                            (size_t)plane * HH + col) = v1;
            }
        }
    }

    // Publish: all CTA stores visible, then release-increment the tile counter
    __threadfence();
    __syncthreads();
    if (tid == 0) red_release_add(&g_flags[mtile], 1u);
}

__device__ void scan_body(char* smr, int sid, const float* __restrict__ x,
                          const float* __restrict__ vf,
                          const float* __restrict__ vr,
                          const float* __restrict__ bf,
                          const float* __restrict__ br,
                          float* __restrict__ out) {
    char* s = smr;  // uses first 24 KB of the dynamic allocation
    const int l = threadIdx.x;          // 0..31 (warp 0 only)
    const int b = sid >> 5;
    const int h0 = (sid & 31) * 32;
    const int h = h0 + l;

    const char* xc_base = (const char*)g_xc + (size_t)b * SS * 4096 + h0 * 4;
    const char* xv_base = (const char*)x + (size_t)b * SS * 4096 + h0 * 4;
    const char* gf_base = (const char*)g_gates + (size_t)b * SS * 4096 + h0 * 2;
    const char* gr_base = gf_base + HH * 2;

    const char* srcp[12];
    uint32_t dsto[12];
#pragma unroll
    for (int i = 0; i < 12; i++) {
        const int gch = i * 32 + l;
        const int t = gch / 24;
        const int j = gch - t * 24;
        const char* p;
        if (j < 8)       p = xc_base + (size_t)t * 4096 + j * 16;
        else if (j < 16) p = xv_base + (size_t)t * 4096 + (j - 8) * 16;
        else if (j < 20) p = gf_base + (size_t)t * 4096 + (j - 16) * 16;
        else             p = gr_base + (size_t)t * 4096 + (j - 20) * 16;
        srcp[i] = p;
        dsto[i] = (uint32_t)(t * REC_B + j * 16);
    }
    const uint32_t sbase = s2u(s);

    const float vfh = 0.5f * vf[h];
    const float vrh = 0.5f * vr[h];
    const float bfh = 0.5f * bf[h];
    const float brh = 0.5f * br[h];
    float* yp = out + (size_t)b * SS * HH + h;

#define WAIT_TILE(mt)                                                         \
    {                                                                         \
        if (l == 0) {                                                         \
            while (ld_acquire(&g_flags[(mt)]) < (uint32_t)NTILES)             \
                __nanosleep(64);                                              \
        }                                                                     \
        __syncwarp();                                                         \
    }

#define LOAD_STAGE(st)                                                        \
    {                                                                         \
        const uint32_t d0 = sbase + (uint32_t)((st) & (SNSTG - 1)) * STAGE_BYTES; \
        const size_t go = (size_t)(st) * (TSTG * 4096);                       \
        _Pragma("unroll") for (int i = 0; i < 12; i++) {                      \
            CP_ASYNC16(d0 + dsto[i], srcp[i] + go);                           \
        }                                                                     \
        CP_COMMIT();                                                          \
    }

    WAIT_TILE(b * 16);                    // stages 0..2 live in local tile 0
    LOAD_STAGE(0);
    LOAD_STAGE(1);
    LOAD_STAGE(2);

    float c = 0.0f;
    const int NST = SS / TSTG;  // 128; 8 stages per 128-row M-tile
    for (int st = 0; st < NST; st++) {
        CP_WAIT2();
        __syncwarp();

        if (st + 3 < NST) {
            if (((st + 3) & 7) == 0) WAIT_TILE(b * 16 + ((st + 3) >> 3));
            LOAD_STAGE(st + 3);
        } else {
            CP_COMMIT();
        }

        const char* sp = s + (st & (SNSTG - 1)) * STAGE_BYTES;
        const int tb = st * TSTG;
#pragma unroll
        for (int t = 0; t < TSTG; t++) {
            const char* rp = sp + t * REC_B;
            const float xc = *(const float*)(rp + l * 4);
            const float xv = *(const float*)(rp + 128 + l * 4);
            const float xf = __half2float(*(const __half*)(rp + 256 + l * 2));
            const float xr = __half2float(*(const __half*)(rp + 320 + l * 2));

            const float xfh = fmaf(0.5f, xf, bfh);
            const float xch = 0.5f * xc;
            const float xrh = fmaf(0.5f, xr, brh);
            const float xvh = 0.5f * xv;

            const float ct = c;
            const float thf = fast_tanh(fmaf(vfh, ct, xfh));
            const float thr = fast_tanh(fmaf(vrh, ct, xrh));
            const float d = fmaf(0.5f, ct, -xch);
            const float m = fmaf(0.5f, ct, xch);
            c = fmaf(thf, d, m);
            const float dr = fmaf(0.5f, c, -xvh);
            const float mr = fmaf(0.5f, c, xvh);
            yp[(size_t)(tb + t) * HH] = fmaf(thr, dr, mr);
        }
        __syncwarp();
    }

    out[(size_t)BB * SS * HH + (size_t)b * HH + h] = c;
}

__global__ void __launch_bounds__(256, 2) sru_joint(
    const float* __restrict__ x, const float* __restrict__ vf,
    const float* __restrict__ vr, const float* __restrict__ bf,
    const float* __restrict__ br, float* __restrict__ out) {
    extern __shared__ __align__(128) char smr[];
    if (blockIdx.x < GEMM_BLOCKS) {
        gemm_body(smr, blockIdx.x);
    } else {
        if (threadIdx.x >= 32) return;    // scan uses warp 0 only; no CTA syncs
        scan_body(smr, blockIdx.x - GEMM_BLOCKS, x, vf, vr, bf, br, out);
    }
}

// ---------------------------------------------------------------------------
// Launch
// ---------------------------------------------------------------------------
extern "C" void kernel_launch(void* const* d_in, const int* in_sizes, int n_in,
                              void* d_out, int out_size) {
    const float* x  = (const float*)d_in[0];
    const float* W  = (const float*)d_in[1];
    const float* vf = (const float*)d_in[2];
    const float* vr = (const float*)d_in[3];
    const float* bf = (const float*)d_in[4];
    const float* br = (const float*)d_in[5];
    float* out = (float*)d_out;

    cvt_fused<<<NA_BLK + NW_BLK, 256>>>(x, W);

    cudaFuncSetAttribute(sru_joint,
                         cudaFuncAttributeMaxDynamicSharedMemorySize, GEMM_SMEM);
    sru_joint<<<GEMM_BLOCKS + (BB * HH) / 32, 256, GEMM_SMEM>>>(x, vf, vr, bf,
                                                                br, out);
}